// round 7
// baseline (speedup 1.0000x reference)
#include <cuda_runtime.h>
#include <cstdint>
#include <cstddef>

// ---------------------------------------------------------------------------
// GCNPrediction: B=16, T=1024, FEAT=768, H=256, C=50, L=2, WIDTH=128, G=32, K=3
// Round 7: tf32 dense GEMMs; fused dist+top3 (no g_dist); semantic branch
// restructured as P/Q GEMM + fused gather+s2 (no build_f, no big s1 GEMM).
// ---------------------------------------------------------------------------

#define BATCH 16
#define TLEN  1024
#define BT    (BATCH * TLEN)       // 16384
#define HCH   256
#define WCH   128
#define KNN   3
#define NCLS  50
#define BTK   (BT * KNN)           // 49152

// ------------------------- scratch (static device memory) ------------------
__device__ float g_h  [BT * HCH];
__device__ float g_t1 [BT * WCH];
__device__ float g_t2 [BT * WCH];
__device__ float g_tC [BT * HCH];
__device__ float g_xx [BT];
__device__ int   g_idx[BT * KNN];
__device__ float g_f  [BT * 768];            // im2col scratch only
__device__ float g_PQ [2 * BT * WCH];        // P | Q
__device__ float g_V  [BTK * WCH];
__device__ float g_W  [BTK * HCH];

#define SEL_EXT (-1)
#define SEL_H    0
#define SEL_T1   1
#define SEL_T2   2
#define SEL_TC   3
#define SEL_F    4
#define SEL_PQ   5
#define SEL_V    6
#define SEL_W    7

__device__ __forceinline__ float* selbuf(int s)
{
    switch (s) {
        case SEL_H:  return g_h;
        case SEL_T1: return g_t1;
        case SEL_T2: return g_t2;
        case SEL_TC: return g_tC;
        case SEL_F:  return g_f;
        case SEL_PQ: return g_PQ;
        case SEL_V:  return g_V;
        case SEL_W:  return g_W;
    }
    return nullptr;
}

__device__ __forceinline__ unsigned f2tf32(float x)
{
    unsigned r;
    asm("cvt.rna.tf32.f32 %0, %1;" : "=r"(r) : "f"(x));
    return r;
}

__device__ __forceinline__ void mma_tf32(
    float& c0, float& c1, float& c2, float& c3,
    unsigned a0, unsigned a1, unsigned a2, unsigned a3,
    unsigned b0, unsigned b1)
{
    asm volatile(
        "mma.sync.aligned.m16n8k8.row.col.f32.tf32.tf32.f32 "
        "{%0,%1,%2,%3}, {%4,%5,%6,%7}, {%8,%9}, {%0,%1,%2,%3};"
        : "+f"(c0), "+f"(c1), "+f"(c2), "+f"(c3)
        : "r"(a0), "r"(a1), "r"(a2), "r"(a3), "r"(b0), "r"(b1));
}

// ------------------------- tf32 tensor-core GEMM ---------------------------
// C[M,N] = act( A[M,K] @ Bw[N,K]^T + bias[n] ), row-major; optional z batch.
// 128x128x16 tile, 256 threads (8 warps of 64x32), double-buffered smem.
// Requires: M % 128 == 0, K % 16 == 0, N even.
#define TFPAD 136
__global__ __launch_bounds__(256, 2) void gemm_tf32_kernel(
    const float* __restrict__ Aext, int Asel, int Aoff, int lda, int Azs,
    const float* __restrict__ Bw, int ldb, int Bzs,
    float* __restrict__ Cext, int Csel, int Coff, int ldc, int Czs,
    int M, int N, int K,
    const float* __restrict__ bias, int bzs, int relu)
{
    const float* A = ((Asel >= 0) ? (selbuf(Asel) + Aoff) : Aext)
                   + (size_t)blockIdx.z * Azs;
    const float* B = Bw + (size_t)blockIdx.z * Bzs;
    float*       C = ((Csel >= 0) ? (selbuf(Csel) + Coff) : Cext)
                   + (size_t)blockIdx.z * Czs;
    const float* bb = bias ? (bias + (size_t)blockIdx.z * bzs) : nullptr;

    __shared__ unsigned As[2][16][TFPAD];
    __shared__ unsigned Bs[2][16][TFPAD];

    const int tid  = threadIdx.x;
    const int lane = tid & 31;
    const int w    = tid >> 5;       // 0..7
    const int wm   = w & 1;          // 0..1  (64-row half)
    const int wn   = w >> 1;         // 0..3  (32-col quarter)
    const int g    = lane >> 2;      // 0..7
    const int tig  = lane & 3;       // 0..3
    const int m0   = blockIdx.y * 128;
    const int n0   = blockIdx.x * 128;

    const int lm = tid & 63;
    const int lf = tid >> 6;                      // 0..3
    const float* arow = A + (size_t)(m0 + lm) * lda + (lf << 2);
    const float* brow = B + (size_t)(n0 + lm) * ldb + (lf << 2);
    const bool bok0 = (n0 + lm)      < N;
    const bool bok1 = (n0 + lm + 64) < N;

    float acc[4][4][4];
#pragma unroll
    for (int i = 0; i < 4; i++)
#pragma unroll
        for (int j = 0; j < 4; j++)
#pragma unroll
            for (int q = 0; q < 4; q++) acc[i][j][q] = 0.f;

    const int nk = K / 16;
    const float4 z4 = make_float4(0.f, 0.f, 0.f, 0.f);

    float4 ra0 = *(const float4*)(arow);
    float4 ra1 = *(const float4*)(arow + (size_t)64 * lda);
    float4 rb0 = bok0 ? *(const float4*)(brow) : z4;
    float4 rb1 = bok1 ? *(const float4*)(brow + (size_t)64 * ldb) : z4;

    for (int kt = 0; kt < nk; kt++) {
        const int buf = kt & 1;
        {
            const int kb = lf << 2;
            As[buf][kb + 0][lm] = f2tf32(ra0.x);
            As[buf][kb + 1][lm] = f2tf32(ra0.y);
            As[buf][kb + 2][lm] = f2tf32(ra0.z);
            As[buf][kb + 3][lm] = f2tf32(ra0.w);
            As[buf][kb + 0][lm + 64] = f2tf32(ra1.x);
            As[buf][kb + 1][lm + 64] = f2tf32(ra1.y);
            As[buf][kb + 2][lm + 64] = f2tf32(ra1.z);
            As[buf][kb + 3][lm + 64] = f2tf32(ra1.w);
            Bs[buf][kb + 0][lm] = f2tf32(rb0.x);
            Bs[buf][kb + 1][lm] = f2tf32(rb0.y);
            Bs[buf][kb + 2][lm] = f2tf32(rb0.z);
            Bs[buf][kb + 3][lm] = f2tf32(rb0.w);
            Bs[buf][kb + 0][lm + 64] = f2tf32(rb1.x);
            Bs[buf][kb + 1][lm + 64] = f2tf32(rb1.y);
            Bs[buf][kb + 2][lm + 64] = f2tf32(rb1.z);
            Bs[buf][kb + 3][lm + 64] = f2tf32(rb1.w);
        }
        __syncthreads();

        if (kt + 1 < nk) {
            const int k0 = (kt + 1) * 16;
            ra0 = *(const float4*)(arow + k0);
            ra1 = *(const float4*)(arow + (size_t)64 * lda + k0);
            rb0 = bok0 ? *(const float4*)(brow + k0) : z4;
            rb1 = bok1 ? *(const float4*)(brow + (size_t)64 * ldb + k0) : z4;
        }

#pragma unroll
        for (int kk = 0; kk < 16; kk += 8) {
            unsigned a[4][4], b[4][2];
            const unsigned* Ak = &As[buf][kk][0];
            const unsigned* Bk = &Bs[buf][kk][0];
#pragma unroll
            for (int i = 0; i < 4; i++) {
                const int mb = wm * 64 + i * 16 + g;
                a[i][0] = Ak[(size_t)tig * TFPAD + mb];
                a[i][1] = Ak[(size_t)tig * TFPAD + mb + 8];
                a[i][2] = Ak[(size_t)(tig + 4) * TFPAD + mb];
                a[i][3] = Ak[(size_t)(tig + 4) * TFPAD + mb + 8];
            }
#pragma unroll
            for (int j = 0; j < 4; j++) {
                const int nb = wn * 32 + j * 8 + g;
                b[j][0] = Bk[(size_t)tig * TFPAD + nb];
                b[j][1] = Bk[(size_t)(tig + 4) * TFPAD + nb];
            }
#pragma unroll
            for (int i = 0; i < 4; i++)
#pragma unroll
                for (int j = 0; j < 4; j++)
                    mma_tf32(acc[i][j][0], acc[i][j][1], acc[i][j][2], acc[i][j][3],
                             a[i][0], a[i][1], a[i][2], a[i][3],
                             b[j][0], b[j][1]);
        }
        __syncthreads();
    }

    float bv[4][2];
#pragma unroll
    for (int j = 0; j < 4; j++) {
        const int col = n0 + wn * 32 + j * 8 + tig * 2;
        const bool ok = bb && (col < N);
        bv[j][0] = ok ? bb[col] : 0.f;
        bv[j][1] = ok ? bb[col + 1] : 0.f;
    }
#pragma unroll
    for (int i = 0; i < 4; i++) {
        const int row = m0 + wm * 64 + i * 16 + g;
#pragma unroll
        for (int j = 0; j < 4; j++) {
            const int col = n0 + wn * 32 + j * 8 + tig * 2;
            if (col >= N) continue;
            float2 lo = make_float2(acc[i][j][0] + bv[j][0],
                                    acc[i][j][1] + bv[j][1]);
            float2 hi = make_float2(acc[i][j][2] + bv[j][0],
                                    acc[i][j][3] + bv[j][1]);
            if (relu) {
                lo.x = fmaxf(lo.x, 0.f); lo.y = fmaxf(lo.y, 0.f);
                hi.x = fmaxf(hi.x, 0.f); hi.y = fmaxf(hi.y, 0.f);
            }
            *(float2*)(C + (size_t)row * ldc + col)       = lo;
            *(float2*)(C + (size_t)(row + 8) * ldc + col) = hi;
        }
    }
}

// ------------------------- fp32 128x128 tile GEMM (final fc only) ----------
__global__ __launch_bounds__(256) void gemm128_kernel(
    const float* __restrict__ Aext, int Asel, int Aoff, int lda,
    const float* __restrict__ Bw, int ldb,
    float* __restrict__ Cext, int Csel, int Coff, int ldc,
    int M, int N, int K,
    const float* __restrict__ bias, int relu)
{
    const float* A = (Asel >= 0) ? (selbuf(Asel) + Aoff) : Aext;
    const float* B = Bw;
    float*       C = (Csel >= 0) ? (selbuf(Csel) + Coff) : Cext;

    __shared__ float As[8][128];
    __shared__ float Bs[8][128];
    const int tid = threadIdx.x;
    const int m0  = blockIdx.y * 128;
    const int n0  = blockIdx.x * 128;
    const int lr  = tid >> 1;
    const int lq  = (tid & 1) << 2;
    const int ty  = tid >> 4;
    const int tx  = tid & 15;

    float acc[8][8];
#pragma unroll
    for (int i = 0; i < 8; i++)
#pragma unroll
        for (int j = 0; j < 8; j++) acc[i][j] = 0.f;

    const bool am_ok = (m0 + lr) < M;
    const bool bn_ok = (n0 + lr) < N;
    const float* aptr = A + (size_t)(m0 + lr) * lda + lq;
    const float* bptr = B + (size_t)(n0 + lr) * ldb + lq;

    for (int k0 = 0; k0 < K; k0 += 8) {
        const float4 va = am_ok ? *(const float4*)(aptr + k0)
                                : make_float4(0.f, 0.f, 0.f, 0.f);
        const float4 vb = bn_ok ? *(const float4*)(bptr + k0)
                                : make_float4(0.f, 0.f, 0.f, 0.f);
        As[lq + 0][lr] = va.x; As[lq + 1][lr] = va.y;
        As[lq + 2][lr] = va.z; As[lq + 3][lr] = va.w;
        Bs[lq + 0][lr] = vb.x; Bs[lq + 1][lr] = vb.y;
        Bs[lq + 2][lr] = vb.z; Bs[lq + 3][lr] = vb.w;
        __syncthreads();
#pragma unroll
        for (int k = 0; k < 8; k++) {
            float af[8], bf[8];
            *(float4*)&af[0] = *(const float4*)&As[k][ty << 3];
            *(float4*)&af[4] = *(const float4*)&As[k][(ty << 3) + 4];
            *(float4*)&bf[0] = *(const float4*)&Bs[k][tx << 3];
            *(float4*)&bf[4] = *(const float4*)&Bs[k][(tx << 3) + 4];
#pragma unroll
            for (int i = 0; i < 8; i++)
#pragma unroll
                for (int j = 0; j < 8; j++)
                    acc[i][j] += af[i] * bf[j];
        }
        __syncthreads();
    }

#pragma unroll
    for (int i = 0; i < 8; i++) {
        const int m = m0 + (ty << 3) + i;
        if (m >= M) continue;
#pragma unroll
        for (int j = 0; j < 8; j++) {
            const int n = n0 + (tx << 3) + j;
            if (n >= N) continue;
            float v = acc[i][j];
            if (bias) v += bias[n];
            if (relu) v = fmaxf(v, 0.f);
            C[(size_t)m * ldc + n] = v;
        }
    }
}

// ------------------------- top-3 helpers -----------------------------------
__device__ __forceinline__ bool better(float v, int i, float w, int j)
{
    return (v > w) || (v == w && i < j);   // JAX top_k: lower index wins ties
}

__device__ __forceinline__ void ins3(float v, int c,
    float& v0, int& i0, float& v1, int& i1, float& v2, int& i2)
{
    if (better(v, c, v0, i0)) { v2 = v1; i2 = i1; v1 = v0; i1 = i0; v0 = v; i0 = c; }
    else if (better(v, c, v1, i1)) { v2 = v1; i2 = i1; v1 = v; i1 = c; }
    else if (better(v, c, v2, i2)) { v2 = v; i2 = c; }
}

// ------------------------- fused kNN dist + top3 ---------------------------
// Per (row-block of 128, batch): compute D[m, 0..1023] in 8 column chunks
// with the fp32 tile body (identical accumulation order to the standalone
// dist kernel), keep running top-3 per row, merge via half-warp shuffles.
// Writes only g_idx. grid (8, 16), 256 threads.
__global__ __launch_bounds__(256) void dist_top3_kernel()
{
    const int b  = blockIdx.y;
    const int m0 = blockIdx.x * 128;
    const float* A   = g_h  + (size_t)b * TLEN * HCH;
    const float* xxb = g_xx + b * TLEN;

    __shared__ float As[8][128];
    __shared__ float Bs[8][128];
    const int tid = threadIdx.x;
    const int lr  = tid >> 1;
    const int lq  = (tid & 1) << 2;
    const int ty  = tid >> 4;
    const int tx  = tid & 15;

    float rv0[8], rv1[8], rv2[8];
    int   ri0[8], ri1[8], ri2[8];
    float xm[8];
#pragma unroll
    for (int i = 0; i < 8; i++) {
        rv0[i] = rv1[i] = rv2[i] = -3.4e38f;
        ri0[i] = ri1[i] = ri2[i] = 0x7fffffff;
        xm[i]  = xxb[m0 + (ty << 3) + i];
    }

    const float* aptr = A + (size_t)(m0 + lr) * HCH + lq;

    for (int chunk = 0; chunk < 8; chunk++) {
        const int n0 = chunk * 128;
        const float* bptr = A + (size_t)(n0 + lr) * HCH + lq;

        float acc[8][8];
#pragma unroll
        for (int i = 0; i < 8; i++)
#pragma unroll
            for (int j = 0; j < 8; j++) acc[i][j] = 0.f;

        for (int k0 = 0; k0 < HCH; k0 += 8) {
            const float4 va = *(const float4*)(aptr + k0);
            const float4 vb = *(const float4*)(bptr + k0);
            As[lq + 0][lr] = va.x; As[lq + 1][lr] = va.y;
            As[lq + 2][lr] = va.z; As[lq + 3][lr] = va.w;
            Bs[lq + 0][lr] = vb.x; Bs[lq + 1][lr] = vb.y;
            Bs[lq + 2][lr] = vb.z; Bs[lq + 3][lr] = vb.w;
            __syncthreads();
#pragma unroll
            for (int k = 0; k < 8; k++) {
                float af[8], bf[8];
                *(float4*)&af[0] = *(const float4*)&As[k][ty << 3];
                *(float4*)&af[4] = *(const float4*)&As[k][(ty << 3) + 4];
                *(float4*)&bf[0] = *(const float4*)&Bs[k][tx << 3];
                *(float4*)&bf[4] = *(const float4*)&Bs[k][(tx << 3) + 4];
#pragma unroll
                for (int i = 0; i < 8; i++)
#pragma unroll
                    for (int j = 0; j < 8; j++)
                        acc[i][j] += af[i] * bf[j];
            }
            __syncthreads();
        }

        // top3 update with finalized distances
#pragma unroll
        for (int j = 0; j < 8; j++) {
            const int col = n0 + (tx << 3) + j;
            const float xn = xxb[col];
#pragma unroll
            for (int i = 0; i < 8; i++) {
                const float d = 2.f * acc[i][j] - xm[i] - xn;
                ins3(d, col, rv0[i], ri0[i], rv1[i], ri1[i], rv2[i], ri2[i]);
            }
        }
    }

    // half-warp butterfly merge over the 16 threads (tx) sharing each row
#pragma unroll
    for (int off = 8; off; off >>= 1) {
#pragma unroll
        for (int i = 0; i < 8; i++) {
            const float w0 = __shfl_xor_sync(0xffffffffu, rv0[i], off);
            const int   j0 = __shfl_xor_sync(0xffffffffu, ri0[i], off);
            const float w1 = __shfl_xor_sync(0xffffffffu, rv1[i], off);
            const int   j1 = __shfl_xor_sync(0xffffffffu, ri1[i], off);
            const float w2 = __shfl_xor_sync(0xffffffffu, rv2[i], off);
            const int   j2 = __shfl_xor_sync(0xffffffffu, ri2[i], off);
            ins3(w0, j0, rv0[i], ri0[i], rv1[i], ri1[i], rv2[i], ri2[i]);
            ins3(w1, j1, rv0[i], ri0[i], rv1[i], ri1[i], rv2[i], ri2[i]);
            ins3(w2, j2, rv0[i], ri0[i], rv1[i], ri1[i], rv2[i], ri2[i]);
        }
    }

    if (tx == 0) {
#pragma unroll
        for (int i = 0; i < 8; i++) {
            const int row = b * TLEN + m0 + (ty << 3) + i;
            g_idx[row * 3 + 0] = ri0[i];
            g_idx[row * 3 + 1] = ri1[i];
            g_idx[row * 3 + 2] = ri2[i];
        }
    }
}

// ------------------------- squared norms -----------------------------------
__global__ __launch_bounds__(256) void xx_kernel()
{
    const int wrp  = threadIdx.x >> 5;
    const int lane = threadIdx.x & 31;
    const int row  = blockIdx.x * 8 + wrp;
    const float4* p = (const float4*)(g_h + (size_t)row * HCH);
    float s = 0.f;
    for (int c = lane; c < HCH / 4; c += 32) {
        const float4 v = p[c];
        s += v.x * v.x + v.y * v.y + v.z * v.z + v.w * v.w;
    }
    for (int o = 16; o; o >>= 1) s += __shfl_xor_sync(0xffffffffu, s, o);
    if (!lane) g_xx[row] = s;
}

// ------------------------- fused gather + s1-combine + s2 ------------------
// u = relu(P[nbr] + Q[ctr] + s1b); v = relu(W2g @ u_g + s2b)  -> g_V
// One thread per (mk, group). P = g_PQ[0..], Q = g_PQ[BT*WCH..].
__global__ __launch_bounds__(256) void gather_s2_kernel(
    const float* __restrict__ b1, const float* __restrict__ w2,
    const float* __restrict__ b2)
{
    const int gid = blockIdx.x * blockDim.x + threadIdx.x;   // BTK * 32
    if (gid >= BTK * 32) return;
    const int g  = gid & 31;
    const int mk = gid >> 5;
    const int bt = mk / 3;
    const int b  = bt >> 10;
    const int nb = g_idx[mk];

    const float4 p  = *(const float4*)(g_PQ + (size_t)(b * TLEN + nb) * WCH + g * 4);
    const float4 q  = *(const float4*)(g_PQ + (size_t)BT * WCH + (size_t)bt * WCH + g * 4);
    const float4 c1 = *(const float4*)(b1 + g * 4);

    float u[4];
    u[0] = fmaxf(p.x + q.x + c1.x, 0.f);
    u[1] = fmaxf(p.y + q.y + c1.y, 0.f);
    u[2] = fmaxf(p.z + q.z + c1.z, 0.f);
    u[3] = fmaxf(p.w + q.w + c1.w, 0.f);

    float4 out;
    float* op = (float*)&out;
#pragma unroll
    for (int o = 0; o < 4; o++) {
        const float4 ww = *(const float4*)(w2 + (g * 4 + o) * 4);
        const float v = u[0] * ww.x + u[1] * ww.y + u[2] * ww.z + u[3] * ww.w
                      + b2[g * 4 + o];
        op[o] = fmaxf(v, 0.f);
    }
    *(float4*)(g_V + (size_t)mk * WCH + g * 4) = out;
}

// ------------------------- t2 grouped conv ---------------------------------
__global__ __launch_bounds__(256) void t2conv_kernel(
    const float* __restrict__ w, const float* __restrict__ bias)
{
    const int gid = blockIdx.x * blockDim.x + threadIdx.x;
    if (gid >= BT * WCH) return;
    const int c  = gid & 127;
    const int bt = gid >> 7;
    const int t  = bt & (TLEN - 1);
    const int g  = c >> 2;
    const float* wc = w + c * 12;
    float acc = bias[c];
#pragma unroll
    for (int kk = 0; kk < 3; kk++) {
        const int tt = t + kk - 1;
        if (tt < 0 || tt >= TLEN) continue;
        const float4 xi = *(const float4*)(g_t1 + (size_t)(bt - t + tt) * WCH + g * 4);
        acc += xi.x * wc[0 * 3 + kk] + xi.y * wc[1 * 3 + kk]
             + xi.z * wc[2 * 3 + kk] + xi.w * wc[3 * 3 + kk];
    }
    g_t2[gid] = fmaxf(acc, 0.f);
}

// ------------------------- im2col for backbone conv ------------------------
__global__ __launch_bounds__(256) void im2col_kernel()
{
    const int gid = blockIdx.x * blockDim.x + threadIdx.x;
    if (gid >= BT * HCH) return;
    const int ci = gid & 255;
    const int m  = gid >> 8;
    const int t  = m & (TLEN - 1);
    float* dst = g_f + (size_t)m * 768 + ci * 3;
#pragma unroll
    for (int kk = 0; kk < 3; kk++) {
        const int tt = t + kk - 1;
        float v = 0.f;
        if (tt >= 0 && tt < TLEN) v = g_tC[(size_t)(m - t + tt) * HCH + ci];
        dst[kk] = v;
    }
}

// ------------------------- combine: h = relu(h + tC + max_k W) -------------
__global__ __launch_bounds__(256) void combine_kernel()
{
    const int gid = blockIdx.x * blockDim.x + threadIdx.x;
    if (gid >= BT * HCH) return;
    const int c = gid & 255;
    const int m = gid >> 8;
    const float* w = g_W + (size_t)m * 3 * HCH + c;
    const float mx = fmaxf(fmaxf(w[0], w[HCH]), w[2 * HCH]);
    g_h[gid] = fmaxf(g_h[gid] + g_tC[gid] + mx, 0.f);
}

// ---------------------------------------------------------------------------
extern "C" void kernel_launch(void* const* d_in, const int* in_sizes, int n_in,
                              void* d_out, int out_size)
{
    (void)in_sizes; (void)n_in; (void)out_size;
    const float* x       = (const float*)d_in[0];
    const float* fc_in_w = (const float*)d_in[1];
    const float* fc_in_b = (const float*)d_in[2];
    const float* conv_w  = (const float*)d_in[3];
    const float* conv_b  = (const float*)d_in[4];
    const float* t1_w    = (const float*)d_in[5];
    const float* t1_b    = (const float*)d_in[6];
    const float* t2_w    = (const float*)d_in[7];
    const float* t2_b    = (const float*)d_in[8];
    const float* t3_w    = (const float*)d_in[9];
    const float* t3_b    = (const float*)d_in[10];
    const float* s1_w    = (const float*)d_in[11];
    const float* s1_b    = (const float*)d_in[12];
    const float* s2_w    = (const float*)d_in[13];
    const float* s2_b    = (const float*)d_in[14];
    const float* s3_w    = (const float*)d_in[15];
    const float* s3_b    = (const float*)d_in[16];
    const float* fc_w    = (const float*)d_in[17];
    const float* fc_b    = (const float*)d_in[18];
    float* out = (float*)d_out;

    // 1) fc_in + relu : [16384,768] @ [256,768]^T -> g_tC   (tf32)
    gemm_tf32_kernel<<<dim3(2, 128), 256>>>(
        x, SEL_EXT, 0, 768, 0, fc_in_w, 768, 0,
        nullptr, SEL_TC, 0, HCH, 0, BT, HCH, 768, fc_in_b, 0, 1);

    // 2) backbone grouped conv: im2col + z-batched tf32 GEMM (N=64, K=192)
    im2col_kernel<<<BT * HCH / 256, 256>>>();
    gemm_tf32_kernel<<<dim3(1, 128, 4), 256>>>(
        nullptr, SEL_F, 0, 768, 192,
        conv_w, 192, 64 * 192,
        nullptr, SEL_H, 0, HCH, 64,
        BT, 64, 192, conv_b, 64, 1);

    // 3) GCNeXt blocks
    for (int l = 0; l < 2; l++) {
        const float* w1 = t1_w + l * WCH * HCH;  const float* b1 = t1_b + l * WCH;
        const float* w2 = t2_w + l * WCH * 12;   const float* b2 = t2_b + l * WCH;
        const float* w3 = t3_w + l * HCH * WCH;  const float* b3 = t3_b + l * HCH;
        const float* sw1 = s1_w + l * WCH * 512; const float* sb1 = s1_b + l * WCH;
        const float* sw2 = s2_w + l * WCH * 4;   const float* sb2 = s2_b + l * WCH;
        const float* sw3 = s3_w + l * HCH * WCH; const float* sb3 = s3_b + l * HCH;

        // temporal branch
        gemm_tf32_kernel<<<dim3(1, 128), 256>>>(
            nullptr, SEL_H, 0, HCH, 0, w1, HCH, 0,
            nullptr, SEL_T1, 0, WCH, 0, BT, WCH, HCH, b1, 0, 1);
        t2conv_kernel<<<BT * WCH / 256, 256>>>(w2, b2);
        gemm_tf32_kernel<<<dim3(2, 128), 256>>>(
            nullptr, SEL_T2, 0, WCH, 0, w3, WCH, 0,
            nullptr, SEL_TC, 0, HCH, 0, BT, HCH, WCH, b3, 0, 0);

        // kNN graph: fused dist + top3 (fp32-exact selection)
        xx_kernel<<<BT / 8, 256>>>();
        dist_top3_kernel<<<dim3(8, 16), 256>>>();

        // semantic branch: P = H@Wn^T, Q = H@Wc^T (z-batched, no bias/relu)
        gemm_tf32_kernel<<<dim3(1, 128, 2), 256>>>(
            nullptr, SEL_H, 0, HCH, 0,
            sw1, 512, 256,                       // z=0: Wn cols, z=1: Wc cols
            nullptr, SEL_PQ, 0, WCH, BT * WCH,
            BT, WCH, HCH, nullptr, 0, 0);
        gather_s2_kernel<<<(BTK * 32 + 255) / 256, 256>>>(sb1, sw2, sb2);
        gemm_tf32_kernel<<<dim3(2, 384), 256>>>(
            nullptr, SEL_V, 0, WCH, 0, sw3, WCH, 0,
            nullptr, SEL_W, 0, HCH, 0, BTK, HCH, WCH, sb3, 0, 0);

        // residual + max-over-k + relu
        combine_kernel<<<BT * HCH / 256, 256>>>();
    }

    // 4) final fc : [16384,256] @ [50,256]^T -> out   (fp32)
    gemm128_kernel<<<dim3(1, 128), 256>>>(
        nullptr, SEL_H, 0, HCH, fc_w, HCH,
        out, SEL_EXT, 0, NCLS, BT, NCLS, HCH, fc_b, 0);
}